// round 9
// baseline (speedup 1.0000x reference)
#include <cuda_runtime.h>
#include <cuda_fp16.h>
#include <math.h>
#include <stdint.h>

#define BB   8
#define SS   1024
#define EE   1024
#define HH   16
#define DHH  64
#define HIDD 4096
#define MTOK (BB*SS)   // 8192 token rows

// ---------------- fp32 scratch ---------------------------------------------
__device__ float g_h2 [(size_t)MTOK*EE];
__device__ float g_a  [(size_t)MTOK*EE];
__device__ float g_f  [(size_t)MTOK*EE];

// ---------------- fp16 activations ------------------------------------------
__device__ __half g_h16 [(size_t)MTOK*EE];
__device__ __half g_q16 [(size_t)MTOK*EE];
__device__ __half g_k16 [(size_t)MTOK*EE];
__device__ __half g_v16 [(size_t)MTOK*EE];
__device__ __half g_o16 [(size_t)MTOK*EE];
__device__ __half g_a16 [(size_t)MTOK*EE];
__device__ __half g_hid16[(size_t)MTOK*HIDD];

// ---------------- fp16 weights ----------------------------------------------
__device__ __half g_w16q[(size_t)EE*EE];
__device__ __half g_w16k[(size_t)EE*EE];
__device__ __half g_w16v[(size_t)EE*EE];
__device__ __half g_w16m[(size_t)EE*EE];
__device__ __half g_w16a[(size_t)HIDD*EE];
__device__ __half g_w16b[(size_t)EE*HIDD];

__device__ __forceinline__ float gelu_exact(float x) {
    return 0.5f * x * (1.0f + erff(x * 0.70710678118654752f));
}

// ============================ PTX helpers (sm_100-safe) =====================
__device__ __forceinline__ uint32_t smem_u32(const void* p) {
    uint32_t a;
    asm("{ .reg .u64 t; cvta.to.shared.u64 t, %1; cvt.u32.u64 %0, t; }"
        : "=r"(a) : "l"(p));
    return a;
}
__device__ __forceinline__ void cp16(uint32_t s, const void* g) {
    asm volatile("cp.async.cg.shared.global [%0], [%1], 16;" :: "r"(s), "l"(g));
}
__device__ __forceinline__ void cp_commit() {
    asm volatile("cp.async.commit_group;" ::: "memory");
}
template<int N>
__device__ __forceinline__ void cp_wait() {
    asm volatile("cp.async.wait_group %0;" :: "n"(N) : "memory");
}
__device__ __forceinline__ void ldsm4(uint32_t& r0, uint32_t& r1,
                                      uint32_t& r2, uint32_t& r3, uint32_t a) {
    asm volatile("ldmatrix.sync.aligned.m8n8.x4.shared.b16 {%0,%1,%2,%3}, [%4];"
                 : "=r"(r0), "=r"(r1), "=r"(r2), "=r"(r3) : "r"(a));
}
__device__ __forceinline__ void ldsm4t(uint32_t& r0, uint32_t& r1,
                                       uint32_t& r2, uint32_t& r3, uint32_t a) {
    asm volatile("ldmatrix.sync.aligned.m8n8.x4.trans.shared.b16 {%0,%1,%2,%3}, [%4];"
                 : "=r"(r0), "=r"(r1), "=r"(r2), "=r"(r3) : "r"(a));
}
__device__ __forceinline__ void mma_f16(float* d, const uint32_t* a, const uint32_t* b) {
    asm volatile(
        "mma.sync.aligned.m16n8k16.row.col.f32.f16.f16.f32 "
        "{%0,%1,%2,%3}, {%4,%5,%6,%7}, {%8,%9}, {%0,%1,%2,%3};"
        : "+f"(d[0]), "+f"(d[1]), "+f"(d[2]), "+f"(d[3])
        : "r"(a[0]), "r"(a[1]), "r"(a[2]), "r"(a[3]), "r"(b[0]), "r"(b[1]));
}
__device__ __forceinline__ uint32_t pack2h(float a, float b) {
    __half2 v = __halves2half2(__float2half_rn(a), __float2half_rn(b));
    return *(uint32_t*)&v;
}

// ============================================================================
// cvt: fp32 -> fp16 (round); cvtw: merged weight converts (segment-indexed)
// ============================================================================
__global__ void __launch_bounds__(256) cvt16_kernel(
    const float* __restrict__ x, __half* __restrict__ y, int n4)
{
    int i = blockIdx.x * 256 + threadIdx.x;
    if (i >= n4) return;
    float4 v = ((const float4*)x)[i];
    ((uint32_t*)y)[2*i]   = pack2h(v.x, v.y);
    ((uint32_t*)y)[2*i+1] = pack2h(v.z, v.w);
}

#define WSEG (EE*EE/4)          // 262144 float4 per square weight
#define WSEGB (HIDD*EE/4)       // 1048576 float4 per FFN weight
__global__ void __launch_bounds__(256) cvtw_kernel(
    const float* __restrict__ wq, const float* __restrict__ wk,
    const float* __restrict__ wv, const float* __restrict__ wm,
    const float* __restrict__ w1, const float* __restrict__ w2,
    __half* __restrict__ yq, __half* __restrict__ yk,
    __half* __restrict__ yv, __half* __restrict__ ym,
    __half* __restrict__ y1, __half* __restrict__ y2)
{
    int i = blockIdx.x * 256 + threadIdx.x;
    const float* src; __half* dst; int off;
    if (i < WSEG)            { src = wq; dst = yq; off = i; }
    else if (i < 2*WSEG)     { src = wk; dst = yk; off = i - WSEG; }
    else if (i < 3*WSEG)     { src = wv; dst = yv; off = i - 2*WSEG; }
    else if (i < 4*WSEG)     { src = wm; dst = ym; off = i - 3*WSEG; }
    else if (i < 4*WSEG + WSEGB) { src = w1; dst = y1; off = i - 4*WSEG; }
    else                     { src = w2; dst = y2; off = i - 4*WSEG - WSEGB; }
    float4 v = ((const float4*)src)[off];
    ((uint32_t*)dst)[2*off]   = pack2h(v.x, v.y);
    ((uint32_t*)dst)[2*off+1] = pack2h(v.z, v.w);
}

// ============================================================================
// fp16 GEMM: C[M,N] = A[M,K] @ W[N,K]^T, fp32 accumulate, single pass.
// CTA 128x256, BK=64, 512 threads (16 warps 4x4, warp tile 32x64), 3 stages.
// ============================================================================
#define TM 128
#define TN 256
#define BK 64
#define ROWB 144                    // 128 B data + 16 B pad
#define A_SUB (128 * ROWB)          // 18432 B
#define W_SUB (256 * ROWB)          // 36864 B
#define STG   (A_SUB + W_SUB)       // 55296 B
#define SMEM_MMA (3 * STG)          // 165888 B

__device__ __forceinline__ void hgemm_core(
    float acc[2][8][4],
    const __half* __restrict__ A, const __half* __restrict__ W,
    int m0, int n0, int K, uint32_t sb)
{
    const int tid  = threadIdx.x;
    const int lane = tid & 31;
    const int wid  = tid >> 5;
    const int wm   = wid & 3;
    const int wn   = wid >> 2;

    const uint32_t a_row  = wm * 32 + (lane & 15);
    const uint32_t a_coff = (lane >> 4) * 16;
    const uint32_t b_row  = wn * 64 + ((lane >> 4) << 3) + (lane & 7);
    const uint32_t b_coff = ((lane >> 3) & 1) * 16;

#pragma unroll
    for (int mt = 0; mt < 2; mt++)
#pragma unroll
        for (int nt = 0; nt < 8; nt++)
#pragma unroll
            for (int r = 0; r < 4; r++) acc[mt][nt][r] = 0.f;

    const int nst = K / BK;
#pragma unroll
    for (int s = 0; s < 2; s++) {
        const uint32_t b = sb + s * STG;
        const int k0 = s * BK;
#pragma unroll
        for (int i = 0; i < 2; i++) {
            int idx = tid + i * 512;
            int lr = idx >> 3, lc = idx & 7;
            cp16(b + lr * ROWB + lc * 16,
                 A + (size_t)(m0 + lr) * K + k0 + lc * 8);
        }
#pragma unroll
        for (int i = 0; i < 4; i++) {
            int idx = tid + i * 512;
            int lr = idx >> 3, lc = idx & 7;
            cp16(b + A_SUB + lr * ROWB + lc * 16,
                 W + (size_t)(n0 + lr) * K + k0 + lc * 8);
        }
        cp_commit();
    }

    int sbuf = 0;
    for (int s = 0; s < nst; s++) {
        cp_wait<1>();
        __syncthreads();

        if (s + 2 < nst) {
            const int nb = (sbuf + 2 >= 3) ? sbuf - 1 : sbuf + 2;
            const uint32_t b = sb + nb * STG;
            const int k0 = (s + 2) * BK;
#pragma unroll
            for (int i = 0; i < 2; i++) {
                int idx = tid + i * 512;
                int lr = idx >> 3, lc = idx & 7;
                cp16(b + lr * ROWB + lc * 16,
                     A + (size_t)(m0 + lr) * K + k0 + lc * 8);
            }
#pragma unroll
            for (int i = 0; i < 4; i++) {
                int idx = tid + i * 512;
                int lr = idx >> 3, lc = idx & 7;
                cp16(b + A_SUB + lr * ROWB + lc * 16,
                     W + (size_t)(n0 + lr) * K + k0 + lc * 8);
            }
            cp_commit();
        }

        const uint32_t bbase = sb + sbuf * STG;
#pragma unroll
        for (int kk = 0; kk < 4; kk++) {
            uint32_t af[2][4];
#pragma unroll
            for (int mt = 0; mt < 2; mt++) {
                uint32_t ad = bbase + (a_row + mt * 16) * ROWB + a_coff + kk * 32;
                ldsm4(af[mt][0], af[mt][1], af[mt][2], af[mt][3], ad);
            }
            uint32_t bf[4][4];
#pragma unroll
            for (int np = 0; np < 4; np++) {
                uint32_t bd = bbase + A_SUB + (b_row + np * 16) * ROWB + b_coff + kk * 32;
                ldsm4(bf[np][0], bf[np][1], bf[np][2], bf[np][3], bd);
            }
#pragma unroll
            for (int mt = 0; mt < 2; mt++)
#pragma unroll
                for (int nt = 0; nt < 8; nt++)
                    mma_f16(acc[mt][nt], af[mt], &bf[nt >> 1][(nt & 1) * 2]);
        }
        __syncthreads();
        sbuf = (sbuf + 1 >= 3) ? 0 : sbuf + 1;
    }
}

// EPI: 0=none,1=+bias,2=+bias+GELU,3=+res ; SOUT: 0=fp32, 1=fp16
template<int EPI, int SOUT>
__device__ __forceinline__ void hgemm_epi(
    float acc[2][8][4], const float* __restrict__ bias, const float* __restrict__ res,
    float* __restrict__ C, __half* __restrict__ C16,
    int m0, int n0, int N)
{
    const int lane = threadIdx.x & 31;
    const int wid  = threadIdx.x >> 5;
    const int wm   = wid & 3, wn = wid >> 2;
#pragma unroll
    for (int mt = 0; mt < 2; mt++) {
        const int rowA = m0 + wm * 32 + mt * 16 + (lane >> 2);
#pragma unroll
        for (int nt = 0; nt < 8; nt++) {
            const int col = n0 + wn * 64 + nt * 8 + (lane & 3) * 2;
            float b0 = 0.f, b1 = 0.f;
            if (EPI == 1 || EPI == 2) { b0 = bias[col]; b1 = bias[col + 1]; }
#pragma unroll
            for (int hf = 0; hf < 2; hf++) {
                const int row = rowA + hf * 8;
                float v0 = acc[mt][nt][hf * 2 + 0];
                float v1 = acc[mt][nt][hf * 2 + 1];
                if (EPI == 1 || EPI == 2) { v0 += b0; v1 += b1; }
                if (EPI == 2) { v0 = gelu_exact(v0); v1 = gelu_exact(v1); }
                const size_t go = (size_t)row * N + col;
                if (EPI == 3) {
                    float2 r2 = *(const float2*)&res[go];
                    v0 += r2.x; v1 += r2.y;
                }
                if (SOUT == 0) {
                    *(float2*)&C[go] = make_float2(v0, v1);
                } else {
                    *(uint32_t*)&C16[go] = pack2h(v0, v1);
                }
            }
        }
    }
}

template<int EPI, int SOUT>
__global__ void __launch_bounds__(512, 1) gemm_f16(
    const __half* __restrict__ A, const __half* __restrict__ W,
    const float* __restrict__ bias, const float* __restrict__ res,
    float* __restrict__ C, __half* __restrict__ C16,
    int M, int N, int K)
{
    extern __shared__ __align__(128) char smem[];
    float acc[2][8][4];
    hgemm_core(acc, A, W, blockIdx.y * TM, blockIdx.x * TN, K, smem_u32(smem));
    hgemm_epi<EPI, SOUT>(acc, bias, res, C, C16, blockIdx.y * TM, blockIdx.x * TN, N);
}

// merged QKV: blockIdx.z selects weight + output
__global__ void __launch_bounds__(512, 1) gemm_qkv(
    const __half* __restrict__ A,
    const __half* __restrict__ W0, const __half* __restrict__ W1,
    const __half* __restrict__ W2,
    __half* __restrict__ o0, __half* __restrict__ o1, __half* __restrict__ o2,
    int M, int N, int K)
{
    extern __shared__ __align__(128) char smem[];
    const int z = blockIdx.z;
    const __half* W = (z == 0) ? W0 : (z == 1) ? W1 : W2;
    __half* O = (z == 0) ? o0 : (z == 1) ? o1 : o2;
    float acc[2][8][4];
    hgemm_core(acc, A, W, blockIdx.y * TM, blockIdx.x * TN, K, smem_u32(smem));
    hgemm_epi<0, 1>(acc, nullptr, nullptr, nullptr, O, blockIdx.y * TM, blockIdx.x * TN, N);
}

// ============================================================================
// fp16 HMMA FlashAttention: CTA = (head FASTEST, qtile 128, batch), 256 thr.
// Head-fastest grid order -> 16 consecutive CTAs share one mask slice (L2 hit).
// ============================================================================
#define AT_ROW 144
#define AT_SUB (64 * AT_ROW)              // 9216 B per 64-row K/V tile
#define AT_QSUB (128 * AT_ROW)            // 18432 B Q tile
#define AT_STG (2 * AT_SUB)               // K | V
#define SMEM_ATT (AT_QSUB + 2 * AT_STG)   // 55296 B

__device__ __forceinline__ void at_ld(
    uint32_t dst, const __half* __restrict__ g, size_t row0, int col0, int tid)
{
#pragma unroll
    for (int i = 0; i < 2; i++) {
        int idx = tid + i * 256;
        int r = idx >> 3, c = idx & 7;
        cp16(dst + r * AT_ROW + c * 16, g + (row0 + r) * EE + col0 + c * 8);
    }
}
__device__ __forceinline__ void at_ldq(
    uint32_t dst, const __half* __restrict__ g, size_t row0, int col0, int tid)
{
#pragma unroll
    for (int i = 0; i < 4; i++) {
        int idx = tid + i * 256;
        int r = idx >> 3, c = idx & 7;
        cp16(dst + r * AT_ROW + c * 16, g + (row0 + r) * EE + col0 + c * 8);
    }
}

__global__ void __launch_bounds__(256, 1) attn_mma(
    const float* __restrict__ mask,
    const __half* __restrict__ q16, const __half* __restrict__ k16,
    const __half* __restrict__ v16, __half* __restrict__ o16)
{
    extern __shared__ __align__(128) char smn[];
    const uint32_t sb = smem_u32(smn);
    const int hd = blockIdx.x, qt = blockIdx.y, b = blockIdx.z;   // head fastest
    const int tid = threadIdx.x;
    const int lane = tid & 31;
    const int w = tid >> 5;
    const int col0 = hd * 64;
    const size_t qrow0 = (size_t)b * SS + (size_t)qt * 128;

    const uint32_t QS  = sb;
    const uint32_t ST0 = sb + AT_QSUB;

    at_ldq(QS, q16, qrow0, col0, tid);
    at_ld(ST0,          k16, (size_t)b * SS, col0, tid);
    at_ld(ST0 + AT_SUB, v16, (size_t)b * SS, col0, tid);
    cp_commit();
    at_ld(ST0 + AT_STG,          k16, (size_t)b * SS + 64, col0, tid);
    at_ld(ST0 + AT_STG + AT_SUB, v16, (size_t)b * SS + 64, col0, tid);
    cp_commit();
    cp_wait<1>();
    __syncthreads();

    uint32_t fq[4][4];
    {
        uint32_t qa = QS + (w * 16 + (lane & 15)) * AT_ROW + (lane >> 4) * 16;
#pragma unroll
        for (int c = 0; c < 4; c++)
            ldsm4(fq[c][0], fq[c][1], fq[c][2], fq[c][3], qa + c * 32);
    }

    float oacc[8][4];
#pragma unroll
    for (int t = 0; t < 8; t++)
#pragma unroll
        for (int r = 0; r < 4; r++) oacc[t][r] = 0.f;
    float rmax0 = -1e30f, rmax1 = -1e30f, rsum0 = 0.f, rsum1 = 0.f;

    const float* mrow0 = mask + ((size_t)b * SS + qt * 128 + w * 16 + (lane >> 2)) * SS
                              + (lane & 3) * 2;
    const float* mrow1 = mrow0 + 8 * SS;

    for (int kt = 0; kt < 16; kt++) {
        if (kt > 0) {
            if (kt + 1 < 16) {
                uint32_t s1 = ST0 + ((kt + 1) & 1) * AT_STG;
                size_t kr = (size_t)b * SS + (size_t)(kt + 1) * 64;
                at_ld(s1,          k16, kr, col0, tid);
                at_ld(s1 + AT_SUB, v16, kr, col0, tid);
                cp_commit();
                cp_wait<1>();
            } else {
                cp_wait<0>();
            }
            __syncthreads();
        }

        const uint32_t kb = ST0 + (kt & 1) * AT_STG;
        const uint32_t vb = kb + AT_SUB;

        // ---- scores = Q K^T ----
        float sacc[8][4];
#pragma unroll
        for (int t = 0; t < 8; t++)
#pragma unroll
            for (int r = 0; r < 4; r++) sacc[t][r] = 0.f;

#pragma unroll
        for (int c = 0; c < 4; c++) {
#pragma unroll
            for (int np = 0; np < 4; np++) {
                uint32_t ka = kb + (np * 16 + ((lane >> 4) << 3) + (lane & 7)) * AT_ROW
                            + ((lane >> 3) & 1) * 16 + c * 32;
                uint32_t kf[4];
                ldsm4(kf[0], kf[1], kf[2], kf[3], ka);
                mma_f16(sacc[2*np],   fq[c], &kf[0]);
                mma_f16(sacc[2*np+1], fq[c], &kf[2]);
            }
        }

        // ---- online masked softmax ----
        const float* mk0 = mrow0 + kt * 64;
        const float* mk1 = mrow1 + kt * 64;
        float tmax0 = -1e30f, tmax1 = -1e30f;
#pragma unroll
        for (int t = 0; t < 8; t++) {
            float2 ma = *(const float2*)(mk0 + t * 8);
            float2 mb = *(const float2*)(mk1 + t * 8);
            sacc[t][0] = sacc[t][0] * 0.125f * ma.x;
            sacc[t][1] = sacc[t][1] * 0.125f * ma.y;
            sacc[t][2] = sacc[t][2] * 0.125f * mb.x;
            sacc[t][3] = sacc[t][3] * 0.125f * mb.y;
            tmax0 = fmaxf(tmax0, fmaxf(sacc[t][0], sacc[t][1]));
            tmax1 = fmaxf(tmax1, fmaxf(sacc[t][2], sacc[t][3]));
        }
        tmax0 = fmaxf(tmax0, __shfl_xor_sync(0xffffffffu, tmax0, 1));
        tmax0 = fmaxf(tmax0, __shfl_xor_sync(0xffffffffu, tmax0, 2));
        tmax1 = fmaxf(tmax1, __shfl_xor_sync(0xffffffffu, tmax1, 1));
        tmax1 = fmaxf(tmax1, __shfl_xor_sync(0xffffffffu, tmax1, 2));
        float nmax0 = fmaxf(rmax0, tmax0), nmax1 = fmaxf(rmax1, tmax1);
        float corr0 = __expf(rmax0 - nmax0), corr1 = __expf(rmax1 - nmax1);
        rmax0 = nmax0; rmax1 = nmax1;

        float ts0 = 0.f, ts1 = 0.f;
#pragma unroll
        for (int t = 0; t < 8; t++) {
            float2 ma = *(const float2*)(mk0 + t * 8);
            float2 mb = *(const float2*)(mk1 + t * 8);
            float e0 = __expf(sacc[t][0] - nmax0) * ma.x;
            float e1 = __expf(sacc[t][1] - nmax0) * ma.y;
            float e2 = __expf(sacc[t][2] - nmax1) * mb.x;
            float e3 = __expf(sacc[t][3] - nmax1) * mb.y;
            ts0 += e0 + e1; ts1 += e2 + e3;
            sacc[t][0] = e0; sacc[t][1] = e1; sacc[t][2] = e2; sacc[t][3] = e3;
        }
        ts0 += __shfl_xor_sync(0xffffffffu, ts0, 1);
        ts0 += __shfl_xor_sync(0xffffffffu, ts0, 2);
        ts1 += __shfl_xor_sync(0xffffffffu, ts1, 1);
        ts1 += __shfl_xor_sync(0xffffffffu, ts1, 2);
        rsum0 = rsum0 * corr0 + ts0;
        rsum1 = rsum1 * corr1 + ts1;
#pragma unroll
        for (int t = 0; t < 8; t++) {
            oacc[t][0] *= corr0; oacc[t][1] *= corr0;
            oacc[t][2] *= corr1; oacc[t][3] *= corr1;
        }

        // ---- O += P V ----
#pragma unroll
        for (int c = 0; c < 4; c++) {
            uint32_t pa[4];
            pa[0] = pack2h(sacc[2*c][0],   sacc[2*c][1]);
            pa[1] = pack2h(sacc[2*c][2],   sacc[2*c][3]);
            pa[2] = pack2h(sacc[2*c+1][0], sacc[2*c+1][1]);
            pa[3] = pack2h(sacc[2*c+1][2], sacc[2*c+1][3]);
#pragma unroll
            for (int nd = 0; nd < 4; nd++) {
                uint32_t va = vb + (c * 16 + ((lane >> 3) & 1) * 8 + (lane & 7)) * AT_ROW
                            + nd * 32 + (lane >> 4) * 16;
                uint32_t vf[4];
                ldsm4t(vf[0], vf[1], vf[2], vf[3], va);
                mma_f16(oacc[2*nd],   pa, &vf[0]);
                mma_f16(oacc[2*nd+1], pa, &vf[2]);
            }
        }
        __syncthreads();
    }

    const float inv0 = 1.0f / (rsum0 + 1e-20f);
    const float inv1 = 1.0f / (rsum1 + 1e-20f);
    const size_t r0g = qrow0 + w * 16 + (lane >> 2);
    const size_t r1g = r0g + 8;
#pragma unroll
    for (int t = 0; t < 8; t++) {
        const int col = col0 + t * 8 + (lane & 3) * 2;
        *(uint32_t*)&o16[r0g * EE + col] = pack2h(oacc[t][0] * inv0, oacc[t][1] * inv0);
        *(uint32_t*)&o16[r1g * EE + col] = pack2h(oacc[t][2] * inv1, oacc[t][3] * inv1);
    }
}

// ============================================================================
// LayerNorm over E=1024; optional gated residual; optional fp16 output.
// ============================================================================
__global__ void __launch_bounds__(256) ln_kernel(
    const float* __restrict__ x, const float* __restrict__ f,
    const float* __restrict__ mask, const float* __restrict__ gamma,
    const float* __restrict__ beta, float* __restrict__ out,
    __half* __restrict__ out16, int useF)
{
    const int row = blockIdx.x;
    const int tid = threadIdx.x;

    float4 v4 = *(const float4*)&x[(size_t)row * EE + tid * 4];
    float v[4] = {v4.x, v4.y, v4.z, v4.w};

    if (useF) {
        const int b = row / SS, s = row % SS;
        const float gate = mask[((size_t)b * SS + (SS - 1)) * SS + s];
        float4 f4 = *(const float4*)&f[(size_t)row * EE + tid * 4];
        v[0] += f4.x * gate; v[1] += f4.y * gate;
        v[2] += f4.z * gate; v[3] += f4.w * gate;
    }

    float s1 = v[0] + v[1] + v[2] + v[3];
    float s2 = v[0]*v[0] + v[1]*v[1] + v[2]*v[2] + v[3]*v[3];
#pragma unroll
    for (int ofs = 16; ofs >= 1; ofs >>= 1) {
        s1 += __shfl_xor_sync(0xffffffffu, s1, ofs);
        s2 += __shfl_xor_sync(0xffffffffu, s2, ofs);
    }
    __shared__ float red1[8], red2[8];
    if ((tid & 31) == 0) { red1[tid >> 5] = s1; red2[tid >> 5] = s2; }
    __syncthreads();
    float t1 = 0.f, t2 = 0.f;
#pragma unroll
    for (int wv = 0; wv < 8; wv++) { t1 += red1[wv]; t2 += red2[wv]; }

    const float mean = t1 * (1.0f / EE);
    const float var  = t2 * (1.0f / EE) - mean * mean;
    const float inv  = rsqrtf(var + 1e-5f);

    float4 g4 = *(const float4*)&gamma[tid * 4];
    float4 b4 = *(const float4*)&beta[tid * 4];
    float o0 = (v[0] - mean) * inv * g4.x + b4.x;
    float o1 = (v[1] - mean) * inv * g4.y + b4.y;
    float o2 = (v[2] - mean) * inv * g4.z + b4.z;
    float o3 = (v[3] - mean) * inv * g4.w + b4.w;
    if (out)
        *(float4*)&out[(size_t)row * EE + tid * 4] = make_float4(o0, o1, o2, o3);
    if (out16) {
        const size_t go = (size_t)row * EE + tid * 4;
        *(uint32_t*)&out16[go]     = pack2h(o0, o1);
        *(uint32_t*)&out16[go + 2] = pack2h(o2, o3);
    }
}

// ============================================================================
extern "C" void kernel_launch(void* const* d_in, const int* in_sizes, int n_in,
                              void* d_out, int out_size)
{
    const float* h    = (const float*)d_in[0];
    const float* mask = (const float*)d_in[1];
    const float* wq   = (const float*)d_in[2];
    const float* wk   = (const float*)d_in[3];
    const float* wv   = (const float*)d_in[4];
    const float* wmh  = (const float*)d_in[5];
    const float* g1   = (const float*)d_in[6];
    const float* be1  = (const float*)d_in[7];
    const float* w1   = (const float*)d_in[8];
    const float* b1   = (const float*)d_in[9];
    const float* w2   = (const float*)d_in[10];
    const float* b2   = (const float*)d_in[11];
    const float* g2   = (const float*)d_in[12];
    const float* be2  = (const float*)d_in[13];
    float* out = (float*)d_out;

    float *h2, *a, *f;
    cudaGetSymbolAddress((void**)&h2, g_h2);
    cudaGetSymbolAddress((void**)&a,  g_a);
    cudaGetSymbolAddress((void**)&f,  g_f);

    __half *h16, *q16, *k16, *v16, *o16, *a16, *hid16;
    __half *w16q, *w16k, *w16v, *w16m, *w16a, *w16b;
    cudaGetSymbolAddress((void**)&h16, g_h16);
    cudaGetSymbolAddress((void**)&q16, g_q16);
    cudaGetSymbolAddress((void**)&k16, g_k16);
    cudaGetSymbolAddress((void**)&v16, g_v16);
    cudaGetSymbolAddress((void**)&o16, g_o16);
    cudaGetSymbolAddress((void**)&a16, g_a16);
    cudaGetSymbolAddress((void**)&hid16, g_hid16);
    cudaGetSymbolAddress((void**)&w16q, g_w16q); cudaGetSymbolAddress((void**)&w16k, g_w16k);
    cudaGetSymbolAddress((void**)&w16v, g_w16v); cudaGetSymbolAddress((void**)&w16m, g_w16m);
    cudaGetSymbolAddress((void**)&w16a, g_w16a); cudaGetSymbolAddress((void**)&w16b, g_w16b);

    cudaFuncSetAttribute(attn_mma, cudaFuncAttributeMaxDynamicSharedMemorySize, SMEM_ATT);
    cudaFuncSetAttribute(gemm_qkv, cudaFuncAttributeMaxDynamicSharedMemorySize, SMEM_MMA);
    cudaFuncSetAttribute(gemm_f16<3,0>, cudaFuncAttributeMaxDynamicSharedMemorySize, SMEM_MMA);
    cudaFuncSetAttribute(gemm_f16<2,1>, cudaFuncAttributeMaxDynamicSharedMemorySize, SMEM_MMA);
    cudaFuncSetAttribute(gemm_f16<1,0>, cudaFuncAttributeMaxDynamicSharedMemorySize, SMEM_MMA);

    // fp32 -> fp16 converts: h (separate) + all six weights (one launch)
    {
        int n4 = MTOK * EE / 4;
        cvt16_kernel<<<(n4 + 255) / 256, 256>>>(h, h16, n4);
        int wtot = 4 * WSEG + 2 * WSEGB;          // 3,145,728 float4 groups
        cvtw_kernel<<<wtot / 256, 256>>>(wq, wk, wv, wmh, w1, w2,
                                         w16q, w16k, w16v, w16m, w16a, w16b);
    }

    dim3 blk(512);
    dim3 gQKV(EE / TN, MTOK / TM, 3);   // (4, 64, 3)
    dim3 gE(EE / TN, MTOK / TM);        // (4, 64)
    dim3 gHid(HIDD / TN, MTOK / TM);    // (16, 64)

    // QKV merged -> fp16
    gemm_qkv<<<gQKV, blk, SMEM_MMA>>>(h16, w16q, w16k, w16v,
                                      q16, k16, v16, MTOK, EE, EE);

    // attention -> o (fp16); head-fastest grid for mask L2 reuse
    attn_mma<<<dim3(HH, SS / 128, BB), dim3(256), SMEM_ATT>>>(mask, q16, k16, v16, o16);

    // mh + residual -> h2 (fp32)
    gemm_f16<3,0><<<gE, blk, SMEM_MMA>>>(o16, w16m, nullptr, h,
                                         h2, nullptr, MTOK, EE, EE);

    // attn_norm -> a fp32 + fp16
    ln_kernel<<<MTOK, 256>>>(h2, nullptr, nullptr, g1, be1, a, a16, 0);

    // FFN1 (+bias+GELU) -> hid fp16
    gemm_f16<2,1><<<gHid, blk, SMEM_MMA>>>(a16, w16a, b1, nullptr,
                                           nullptr, hid16, MTOK, HIDD, EE);
    // FFN2 (+bias) -> f fp32
    gemm_f16<1,0><<<gE, blk, SMEM_MMA>>>(hid16, w16b, b2, nullptr,
                                         f, nullptr, MTOK, EE, HIDD);

    // gated residual + ffn_norm -> out
    ln_kernel<<<MTOK, 256>>>(a, f, mask, g2, be2, out, nullptr, 1);
}

// round 10
// speedup vs baseline: 1.0706x; 1.0706x over previous
#include <cuda_runtime.h>
#include <cuda_fp16.h>
#include <math.h>
#include <stdint.h>

#define BB   8
#define SS   1024
#define EE   1024
#define HH   16
#define DHH  64
#define HIDD 4096
#define MTOK (BB*SS)   // 8192 token rows

// ---------------- fp32 scratch ---------------------------------------------
__device__ float g_h2 [(size_t)MTOK*EE];
__device__ float g_a  [(size_t)MTOK*EE];
__device__ float g_f  [(size_t)MTOK*EE];

// ---------------- fp16 activations ------------------------------------------
__device__ __half g_h16 [(size_t)MTOK*EE];
__device__ __half g_q16 [(size_t)MTOK*EE];
__device__ __half g_k16 [(size_t)MTOK*EE];
__device__ __half g_v16 [(size_t)MTOK*EE];
__device__ __half g_o16 [(size_t)MTOK*EE];
__device__ __half g_a16 [(size_t)MTOK*EE];
__device__ __half g_hid16[(size_t)MTOK*HIDD];

// ---------------- fp16 weights ----------------------------------------------
__device__ __half g_w16q[(size_t)EE*EE];
__device__ __half g_w16k[(size_t)EE*EE];
__device__ __half g_w16v[(size_t)EE*EE];
__device__ __half g_w16m[(size_t)EE*EE];
__device__ __half g_w16a[(size_t)HIDD*EE];
__device__ __half g_w16b[(size_t)EE*HIDD];

__device__ __forceinline__ float gelu_exact(float x) {
    return 0.5f * x * (1.0f + erff(x * 0.70710678118654752f));
}

// ============================ PTX helpers (sm_100-safe) =====================
__device__ __forceinline__ uint32_t smem_u32(const void* p) {
    uint32_t a;
    asm("{ .reg .u64 t; cvta.to.shared.u64 t, %1; cvt.u32.u64 %0, t; }"
        : "=r"(a) : "l"(p));
    return a;
}
__device__ __forceinline__ void cp16(uint32_t s, const void* g) {
    asm volatile("cp.async.cg.shared.global [%0], [%1], 16;" :: "r"(s), "l"(g));
}
__device__ __forceinline__ void cp_commit() {
    asm volatile("cp.async.commit_group;" ::: "memory");
}
template<int N>
__device__ __forceinline__ void cp_wait() {
    asm volatile("cp.async.wait_group %0;" :: "n"(N) : "memory");
}
__device__ __forceinline__ void ldsm4(uint32_t& r0, uint32_t& r1,
                                      uint32_t& r2, uint32_t& r3, uint32_t a) {
    asm volatile("ldmatrix.sync.aligned.m8n8.x4.shared.b16 {%0,%1,%2,%3}, [%4];"
                 : "=r"(r0), "=r"(r1), "=r"(r2), "=r"(r3) : "r"(a));
}
__device__ __forceinline__ void ldsm4t(uint32_t& r0, uint32_t& r1,
                                       uint32_t& r2, uint32_t& r3, uint32_t a) {
    asm volatile("ldmatrix.sync.aligned.m8n8.x4.trans.shared.b16 {%0,%1,%2,%3}, [%4];"
                 : "=r"(r0), "=r"(r1), "=r"(r2), "=r"(r3) : "r"(a));
}
__device__ __forceinline__ void mma_f16(float* d, const uint32_t* a, const uint32_t* b) {
    asm volatile(
        "mma.sync.aligned.m16n8k16.row.col.f32.f16.f16.f32 "
        "{%0,%1,%2,%3}, {%4,%5,%6,%7}, {%8,%9}, {%0,%1,%2,%3};"
        : "+f"(d[0]), "+f"(d[1]), "+f"(d[2]), "+f"(d[3])
        : "r"(a[0]), "r"(a[1]), "r"(a[2]), "r"(a[3]), "r"(b[0]), "r"(b[1]));
}
__device__ __forceinline__ uint32_t pack2h(float a, float b) {
    __half2 v = __halves2half2(__float2half_rn(a), __float2half_rn(b));
    return *(uint32_t*)&v;
}

// ============================================================================
// cvt: fp32 -> fp16 (round); cvtw: merged weight converts (segment-indexed)
// ============================================================================
__global__ void __launch_bounds__(256) cvt16_kernel(
    const float* __restrict__ x, __half* __restrict__ y, int n4)
{
    int i = blockIdx.x * 256 + threadIdx.x;
    if (i >= n4) return;
    float4 v = ((const float4*)x)[i];
    ((uint32_t*)y)[2*i]   = pack2h(v.x, v.y);
    ((uint32_t*)y)[2*i+1] = pack2h(v.z, v.w);
}

#define WSEG (EE*EE/4)          // 262144 float4 per square weight
#define WSEGB (HIDD*EE/4)       // 1048576 float4 per FFN weight
__global__ void __launch_bounds__(256) cvtw_kernel(
    const float* __restrict__ wq, const float* __restrict__ wk,
    const float* __restrict__ wv, const float* __restrict__ wm,
    const float* __restrict__ w1, const float* __restrict__ w2,
    __half* __restrict__ yq, __half* __restrict__ yk,
    __half* __restrict__ yv, __half* __restrict__ ym,
    __half* __restrict__ y1, __half* __restrict__ y2)
{
    int i = blockIdx.x * 256 + threadIdx.x;
    const float* src; __half* dst; int off;
    if (i < WSEG)            { src = wq; dst = yq; off = i; }
    else if (i < 2*WSEG)     { src = wk; dst = yk; off = i - WSEG; }
    else if (i < 3*WSEG)     { src = wv; dst = yv; off = i - 2*WSEG; }
    else if (i < 4*WSEG)     { src = wm; dst = ym; off = i - 3*WSEG; }
    else if (i < 4*WSEG + WSEGB) { src = w1; dst = y1; off = i - 4*WSEG; }
    else                     { src = w2; dst = y2; off = i - 4*WSEG - WSEGB; }
    float4 v = ((const float4*)src)[off];
    ((uint32_t*)dst)[2*off]   = pack2h(v.x, v.y);
    ((uint32_t*)dst)[2*off+1] = pack2h(v.z, v.w);
}

// ============================================================================
// fp16 GEMM: C[M,N] = A[M,K] @ W[N,K]^T, fp32 accumulate, single pass.
// CTA 128x256, BK=64, 512 threads (16 warps 4x4, warp tile 32x64), 3 stages.
// ============================================================================
#define TM 128
#define TN 256
#define BK 64
#define ROWB 144                    // 128 B data + 16 B pad
#define A_SUB (128 * ROWB)          // 18432 B
#define W_SUB (256 * ROWB)          // 36864 B
#define STG   (A_SUB + W_SUB)       // 55296 B
#define SMEM_MMA (3 * STG)          // 165888 B

__device__ __forceinline__ void hgemm_core(
    float acc[2][8][4],
    const __half* __restrict__ A, const __half* __restrict__ W,
    int m0, int n0, int K, uint32_t sb)
{
    const int tid  = threadIdx.x;
    const int lane = tid & 31;
    const int wid  = tid >> 5;
    const int wm   = wid & 3;
    const int wn   = wid >> 2;

    const uint32_t a_row  = wm * 32 + (lane & 15);
    const uint32_t a_coff = (lane >> 4) * 16;
    const uint32_t b_row  = wn * 64 + ((lane >> 4) << 3) + (lane & 7);
    const uint32_t b_coff = ((lane >> 3) & 1) * 16;

#pragma unroll
    for (int mt = 0; mt < 2; mt++)
#pragma unroll
        for (int nt = 0; nt < 8; nt++)
#pragma unroll
            for (int r = 0; r < 4; r++) acc[mt][nt][r] = 0.f;

    const int nst = K / BK;
#pragma unroll
    for (int s = 0; s < 2; s++) {
        const uint32_t b = sb + s * STG;
        const int k0 = s * BK;
#pragma unroll
        for (int i = 0; i < 2; i++) {
            int idx = tid + i * 512;
            int lr = idx >> 3, lc = idx & 7;
            cp16(b + lr * ROWB + lc * 16,
                 A + (size_t)(m0 + lr) * K + k0 + lc * 8);
        }
#pragma unroll
        for (int i = 0; i < 4; i++) {
            int idx = tid + i * 512;
            int lr = idx >> 3, lc = idx & 7;
            cp16(b + A_SUB + lr * ROWB + lc * 16,
                 W + (size_t)(n0 + lr) * K + k0 + lc * 8);
        }
        cp_commit();
    }

    int sbuf = 0;
    for (int s = 0; s < nst; s++) {
        cp_wait<1>();
        __syncthreads();

        if (s + 2 < nst) {
            const int nb = (sbuf + 2 >= 3) ? sbuf - 1 : sbuf + 2;
            const uint32_t b = sb + nb * STG;
            const int k0 = (s + 2) * BK;
#pragma unroll
            for (int i = 0; i < 2; i++) {
                int idx = tid + i * 512;
                int lr = idx >> 3, lc = idx & 7;
                cp16(b + lr * ROWB + lc * 16,
                     A + (size_t)(m0 + lr) * K + k0 + lc * 8);
            }
#pragma unroll
            for (int i = 0; i < 4; i++) {
                int idx = tid + i * 512;
                int lr = idx >> 3, lc = idx & 7;
                cp16(b + A_SUB + lr * ROWB + lc * 16,
                     W + (size_t)(n0 + lr) * K + k0 + lc * 8);
            }
            cp_commit();
        }

        const uint32_t bbase = sb + sbuf * STG;
#pragma unroll
        for (int kk = 0; kk < 4; kk++) {
            uint32_t af[2][4];
#pragma unroll
            for (int mt = 0; mt < 2; mt++) {
                uint32_t ad = bbase + (a_row + mt * 16) * ROWB + a_coff + kk * 32;
                ldsm4(af[mt][0], af[mt][1], af[mt][2], af[mt][3], ad);
            }
            uint32_t bf[4][4];
#pragma unroll
            for (int np = 0; np < 4; np++) {
                uint32_t bd = bbase + A_SUB + (b_row + np * 16) * ROWB + b_coff + kk * 32;
                ldsm4(bf[np][0], bf[np][1], bf[np][2], bf[np][3], bd);
            }
#pragma unroll
            for (int mt = 0; mt < 2; mt++)
#pragma unroll
                for (int nt = 0; nt < 8; nt++)
                    mma_f16(acc[mt][nt], af[mt], &bf[nt >> 1][(nt & 1) * 2]);
        }
        __syncthreads();
        sbuf = (sbuf + 1 >= 3) ? 0 : sbuf + 1;
    }
}

// EPI: 0=none,1=+bias,2=+bias+GELU,3=+res ; SOUT: 0=fp32, 1=fp16
template<int EPI, int SOUT>
__device__ __forceinline__ void hgemm_epi(
    float acc[2][8][4], const float* __restrict__ bias, const float* __restrict__ res,
    float* __restrict__ C, __half* __restrict__ C16,
    int m0, int n0, int N)
{
    const int lane = threadIdx.x & 31;
    const int wid  = threadIdx.x >> 5;
    const int wm   = wid & 3, wn = wid >> 2;
#pragma unroll
    for (int mt = 0; mt < 2; mt++) {
        const int rowA = m0 + wm * 32 + mt * 16 + (lane >> 2);
#pragma unroll
        for (int nt = 0; nt < 8; nt++) {
            const int col = n0 + wn * 64 + nt * 8 + (lane & 3) * 2;
            float b0 = 0.f, b1 = 0.f;
            if (EPI == 1 || EPI == 2) { b0 = bias[col]; b1 = bias[col + 1]; }
#pragma unroll
            for (int hf = 0; hf < 2; hf++) {
                const int row = rowA + hf * 8;
                float v0 = acc[mt][nt][hf * 2 + 0];
                float v1 = acc[mt][nt][hf * 2 + 1];
                if (EPI == 1 || EPI == 2) { v0 += b0; v1 += b1; }
                if (EPI == 2) { v0 = gelu_exact(v0); v1 = gelu_exact(v1); }
                const size_t go = (size_t)row * N + col;
                if (EPI == 3) {
                    float2 r2 = *(const float2*)&res[go];
                    v0 += r2.x; v1 += r2.y;
                }
                if (SOUT == 0) {
                    *(float2*)&C[go] = make_float2(v0, v1);
                } else {
                    *(uint32_t*)&C16[go] = pack2h(v0, v1);
                }
            }
        }
    }
}

template<int EPI, int SOUT>
__global__ void __launch_bounds__(512, 1) gemm_f16(
    const __half* __restrict__ A, const __half* __restrict__ W,
    const float* __restrict__ bias, const float* __restrict__ res,
    float* __restrict__ C, __half* __restrict__ C16,
    int M, int N, int K)
{
    extern __shared__ __align__(128) char smem[];
    float acc[2][8][4];
    hgemm_core(acc, A, W, blockIdx.y * TM, blockIdx.x * TN, K, smem_u32(smem));
    hgemm_epi<EPI, SOUT>(acc, bias, res, C, C16, blockIdx.y * TM, blockIdx.x * TN, N);
}

// merged QKV: blockIdx.z selects weight + output
__global__ void __launch_bounds__(512, 1) gemm_qkv(
    const __half* __restrict__ A,
    const __half* __restrict__ W0, const __half* __restrict__ W1,
    const __half* __restrict__ W2,
    __half* __restrict__ o0, __half* __restrict__ o1, __half* __restrict__ o2,
    int M, int N, int K)
{
    extern __shared__ __align__(128) char smem[];
    const int z = blockIdx.z;
    const __half* W = (z == 0) ? W0 : (z == 1) ? W1 : W2;
    __half* O = (z == 0) ? o0 : (z == 1) ? o1 : o2;
    float acc[2][8][4];
    hgemm_core(acc, A, W, blockIdx.y * TM, blockIdx.x * TN, K, smem_u32(smem));
    hgemm_epi<0, 1>(acc, nullptr, nullptr, nullptr, O, blockIdx.y * TM, blockIdx.x * TN, N);
}

// ============================================================================
// fp16 HMMA FlashAttention: CTA = (head, qtile 128, batch), 256 thr, 8 warps.
// Q fragments re-loaded from smem per K-chunk (saves 16 regs) and
// __launch_bounds__(256,2) -> 2 CTAs/SM (occupancy 12.5% -> 25%).
// ============================================================================
#define AT_ROW 144
#define AT_SUB (64 * AT_ROW)              // 9216 B per 64-row K/V tile
#define AT_QSUB (128 * AT_ROW)            // 18432 B Q tile
#define AT_STG (2 * AT_SUB)               // K | V
#define SMEM_ATT (AT_QSUB + 2 * AT_STG)   // 55296 B  (x2 CTAs = 110592 B/SM)

__device__ __forceinline__ void at_ld(
    uint32_t dst, const __half* __restrict__ g, size_t row0, int col0, int tid)
{
#pragma unroll
    for (int i = 0; i < 2; i++) {
        int idx = tid + i * 256;
        int r = idx >> 3, c = idx & 7;
        cp16(dst + r * AT_ROW + c * 16, g + (row0 + r) * EE + col0 + c * 8);
    }
}
__device__ __forceinline__ void at_ldq(
    uint32_t dst, const __half* __restrict__ g, size_t row0, int col0, int tid)
{
#pragma unroll
    for (int i = 0; i < 4; i++) {
        int idx = tid + i * 256;
        int r = idx >> 3, c = idx & 7;
        cp16(dst + r * AT_ROW + c * 16, g + (row0 + r) * EE + col0 + c * 8);
    }
}

__global__ void __launch_bounds__(256, 2) attn_mma(
    const float* __restrict__ mask,
    const __half* __restrict__ q16, const __half* __restrict__ k16,
    const __half* __restrict__ v16, __half* __restrict__ o16)
{
    extern __shared__ __align__(128) char smn[];
    const uint32_t sb = smem_u32(smn);
    const int hd = blockIdx.x, qt = blockIdx.y, b = blockIdx.z;
    const int tid = threadIdx.x;
    const int lane = tid & 31;
    const int w = tid >> 5;
    const int col0 = hd * 64;
    const size_t qrow0 = (size_t)b * SS + (size_t)qt * 128;

    const uint32_t QS  = sb;
    const uint32_t ST0 = sb + AT_QSUB;

    at_ldq(QS, q16, qrow0, col0, tid);
    at_ld(ST0,          k16, (size_t)b * SS, col0, tid);
    at_ld(ST0 + AT_SUB, v16, (size_t)b * SS, col0, tid);
    cp_commit();
    at_ld(ST0 + AT_STG,          k16, (size_t)b * SS + 64, col0, tid);
    at_ld(ST0 + AT_STG + AT_SUB, v16, (size_t)b * SS + 64, col0, tid);
    cp_commit();
    cp_wait<1>();
    __syncthreads();

    // Q fragment base address (fragments reloaded per chunk inside the loop)
    const uint32_t qbase = QS + (w * 16 + (lane & 15)) * AT_ROW + (lane >> 4) * 16;

    float oacc[8][4];
#pragma unroll
    for (int t = 0; t < 8; t++)
#pragma unroll
        for (int r = 0; r < 4; r++) oacc[t][r] = 0.f;
    float rmax0 = -1e30f, rmax1 = -1e30f, rsum0 = 0.f, rsum1 = 0.f;

    const float* mrow0 = mask + ((size_t)b * SS + qt * 128 + w * 16 + (lane >> 2)) * SS
                              + (lane & 3) * 2;
    const float* mrow1 = mrow0 + 8 * SS;

    for (int kt = 0; kt < 16; kt++) {
        if (kt > 0) {
            if (kt + 1 < 16) {
                uint32_t s1 = ST0 + ((kt + 1) & 1) * AT_STG;
                size_t kr = (size_t)b * SS + (size_t)(kt + 1) * 64;
                at_ld(s1,          k16, kr, col0, tid);
                at_ld(s1 + AT_SUB, v16, kr, col0, tid);
                cp_commit();
                cp_wait<1>();
            } else {
                cp_wait<0>();
            }
            __syncthreads();
        }

        const uint32_t kb = ST0 + (kt & 1) * AT_STG;
        const uint32_t vb = kb + AT_SUB;

        // ---- scores = Q K^T (Q fragment reloaded per chunk) ----
        float sacc[8][4];
#pragma unroll
        for (int t = 0; t < 8; t++)
#pragma unroll
            for (int r = 0; r < 4; r++) sacc[t][r] = 0.f;

#pragma unroll
        for (int c = 0; c < 4; c++) {
            uint32_t fq[4];
            ldsm4(fq[0], fq[1], fq[2], fq[3], qbase + c * 32);
#pragma unroll
            for (int np = 0; np < 4; np++) {
                uint32_t ka = kb + (np * 16 + ((lane >> 4) << 3) + (lane & 7)) * AT_ROW
                            + ((lane >> 3) & 1) * 16 + c * 32;
                uint32_t kf[4];
                ldsm4(kf[0], kf[1], kf[2], kf[3], ka);
                mma_f16(sacc[2*np],   fq, &kf[0]);
                mma_f16(sacc[2*np+1], fq, &kf[2]);
            }
        }

        // ---- online masked softmax ----
        const float* mk0 = mrow0 + kt * 64;
        const float* mk1 = mrow1 + kt * 64;
        float tmax0 = -1e30f, tmax1 = -1e30f;
#pragma unroll
        for (int t = 0; t < 8; t++) {
            float2 ma = *(const float2*)(mk0 + t * 8);
            float2 mb = *(const float2*)(mk1 + t * 8);
            sacc[t][0] = sacc[t][0] * 0.125f * ma.x;
            sacc[t][1] = sacc[t][1] * 0.125f * ma.y;
            sacc[t][2] = sacc[t][2] * 0.125f * mb.x;
            sacc[t][3] = sacc[t][3] * 0.125f * mb.y;
            tmax0 = fmaxf(tmax0, fmaxf(sacc[t][0], sacc[t][1]));
            tmax1 = fmaxf(tmax1, fmaxf(sacc[t][2], sacc[t][3]));
        }
        tmax0 = fmaxf(tmax0, __shfl_xor_sync(0xffffffffu, tmax0, 1));
        tmax0 = fmaxf(tmax0, __shfl_xor_sync(0xffffffffu, tmax0, 2));
        tmax1 = fmaxf(tmax1, __shfl_xor_sync(0xffffffffu, tmax1, 1));
        tmax1 = fmaxf(tmax1, __shfl_xor_sync(0xffffffffu, tmax1, 2));
        float nmax0 = fmaxf(rmax0, tmax0), nmax1 = fmaxf(rmax1, tmax1);
        float corr0 = __expf(rmax0 - nmax0), corr1 = __expf(rmax1 - nmax1);
        rmax0 = nmax0; rmax1 = nmax1;

        float ts0 = 0.f, ts1 = 0.f;
#pragma unroll
        for (int t = 0; t < 8; t++) {
            float2 ma = *(const float2*)(mk0 + t * 8);
            float2 mb = *(const float2*)(mk1 + t * 8);
            float e0 = __expf(sacc[t][0] - nmax0) * ma.x;
            float e1 = __expf(sacc[t][1] - nmax0) * ma.y;
            float e2 = __expf(sacc[t][2] - nmax1) * mb.x;
            float e3 = __expf(sacc[t][3] - nmax1) * mb.y;
            ts0 += e0 + e1; ts1 += e2 + e3;
            sacc[t][0] = e0; sacc[t][1] = e1; sacc[t][2] = e2; sacc[t][3] = e3;
        }
        ts0 += __shfl_xor_sync(0xffffffffu, ts0, 1);
        ts0 += __shfl_xor_sync(0xffffffffu, ts0, 2);
        ts1 += __shfl_xor_sync(0xffffffffu, ts1, 1);
        ts1 += __shfl_xor_sync(0xffffffffu, ts1, 2);
        rsum0 = rsum0 * corr0 + ts0;
        rsum1 = rsum1 * corr1 + ts1;
#pragma unroll
        for (int t = 0; t < 8; t++) {
            oacc[t][0] *= corr0; oacc[t][1] *= corr0;
            oacc[t][2] *= corr1; oacc[t][3] *= corr1;
        }

        // ---- O += P V ----
#pragma unroll
        for (int c = 0; c < 4; c++) {
            uint32_t pa[4];
            pa[0] = pack2h(sacc[2*c][0],   sacc[2*c][1]);
            pa[1] = pack2h(sacc[2*c][2],   sacc[2*c][3]);
            pa[2] = pack2h(sacc[2*c+1][0], sacc[2*c+1][1]);
            pa[3] = pack2h(sacc[2*c+1][2], sacc[2*c+1][3]);
#pragma unroll
            for (int nd = 0; nd < 4; nd++) {
                uint32_t va = vb + (c * 16 + ((lane >> 3) & 1) * 8 + (lane & 7)) * AT_ROW
                            + nd * 32 + (lane >> 4) * 16;
                uint32_t vf[4];
                ldsm4t(vf[0], vf[1], vf[2], vf[3], va);
                mma_f16(oacc[2*nd],   pa, &vf[0]);
                mma_f16(oacc[2*nd+1], pa, &vf[2]);
            }
        }
        __syncthreads();
    }

    const float inv0 = 1.0f / (rsum0 + 1e-20f);
    const float inv1 = 1.0f / (rsum1 + 1e-20f);
    const size_t r0g = qrow0 + w * 16 + (lane >> 2);
    const size_t r1g = r0g + 8;
#pragma unroll
    for (int t = 0; t < 8; t++) {
        const int col = col0 + t * 8 + (lane & 3) * 2;
        *(uint32_t*)&o16[r0g * EE + col] = pack2h(oacc[t][0] * inv0, oacc[t][1] * inv0);
        *(uint32_t*)&o16[r1g * EE + col] = pack2h(oacc[t][2] * inv1, oacc[t][3] * inv1);
    }
}

// ============================================================================
// LayerNorm over E=1024; optional gated residual; optional fp16 output.
// ============================================================================
__global__ void __launch_bounds__(256) ln_kernel(
    const float* __restrict__ x, const float* __restrict__ f,
    const float* __restrict__ mask, const float* __restrict__ gamma,
    const float* __restrict__ beta, float* __restrict__ out,
    __half* __restrict__ out16, int useF)
{
    const int row = blockIdx.x;
    const int tid = threadIdx.x;

    float4 v4 = *(const float4*)&x[(size_t)row * EE + tid * 4];
    float v[4] = {v4.x, v4.y, v4.z, v4.w};

    if (useF) {
        const int b = row / SS, s = row % SS;
        const float gate = mask[((size_t)b * SS + (SS - 1)) * SS + s];
        float4 f4 = *(const float4*)&f[(size_t)row * EE + tid * 4];
        v[0] += f4.x * gate; v[1] += f4.y * gate;
        v[2] += f4.z * gate; v[3] += f4.w * gate;
    }

    float s1 = v[0] + v[1] + v[2] + v[3];
    float s2 = v[0]*v[0] + v[1]*v[1] + v[2]*v[2] + v[3]*v[3];
#pragma unroll
    for (int ofs = 16; ofs >= 1; ofs >>= 1) {
        s1 += __shfl_xor_sync(0xffffffffu, s1, ofs);
        s2 += __shfl_xor_sync(0xffffffffu, s2, ofs);
    }
    __shared__ float red1[8], red2[8];
    if ((tid & 31) == 0) { red1[tid >> 5] = s1; red2[tid >> 5] = s2; }
    __syncthreads();
    float t1 = 0.f, t2 = 0.f;
#pragma unroll
    for (int wv = 0; wv < 8; wv++) { t1 += red1[wv]; t2 += red2[wv]; }

    const float mean = t1 * (1.0f / EE);
    const float var  = t2 * (1.0f / EE) - mean * mean;
    const float inv  = rsqrtf(var + 1e-5f);

    float4 g4 = *(const float4*)&gamma[tid * 4];
    float4 b4 = *(const float4*)&beta[tid * 4];
    float o0 = (v[0] - mean) * inv * g4.x + b4.x;
    float o1 = (v[1] - mean) * inv * g4.y + b4.y;
    float o2 = (v[2] - mean) * inv * g4.z + b4.z;
    float o3 = (v[3] - mean) * inv * g4.w + b4.w;
    if (out)
        *(float4*)&out[(size_t)row * EE + tid * 4] = make_float4(o0, o1, o2, o3);
    if (out16) {
        const size_t go = (size_t)row * EE + tid * 4;
        *(uint32_t*)&out16[go]     = pack2h(o0, o1);
        *(uint32_t*)&out16[go + 2] = pack2h(o2, o3);
    }
}

// ============================================================================
extern "C" void kernel_launch(void* const* d_in, const int* in_sizes, int n_in,
                              void* d_out, int out_size)
{
    const float* h    = (const float*)d_in[0];
    const float* mask = (const float*)d_in[1];
    const float* wq   = (const float*)d_in[2];
    const float* wk   = (const float*)d_in[3];
    const float* wv   = (const float*)d_in[4];
    const float* wmh  = (const float*)d_in[5];
    const float* g1   = (const float*)d_in[6];
    const float* be1  = (const float*)d_in[7];
    const float* w1   = (const float*)d_in[8];
    const float* b1   = (const float*)d_in[9];
    const float* w2   = (const float*)d_in[10];
    const float* b2   = (const float*)d_in[11];
    const float* g2   = (const float*)d_in[12];
    const float* be2  = (const float*)d_in[13];
    float* out = (float*)d_out;

    float *h2, *a, *f;
    cudaGetSymbolAddress((void**)&h2, g_h2);
    cudaGetSymbolAddress((void**)&a,  g_a);
    cudaGetSymbolAddress((void**)&f,  g_f);

    __half *h16, *q16, *k16, *v16, *o16, *a16, *hid16;
    __half *w16q, *w16k, *w16v, *w16m, *w16a, *w16b;
    cudaGetSymbolAddress((void**)&h16, g_h16);
    cudaGetSymbolAddress((void**)&q16, g_q16);
    cudaGetSymbolAddress((void**)&k16, g_k16);
    cudaGetSymbolAddress((void**)&v16, g_v16);
    cudaGetSymbolAddress((void**)&o16, g_o16);
    cudaGetSymbolAddress((void**)&a16, g_a16);
    cudaGetSymbolAddress((void**)&hid16, g_hid16);
    cudaGetSymbolAddress((void**)&w16q, g_w16q); cudaGetSymbolAddress((void**)&w16k, g_w16k);
    cudaGetSymbolAddress((void**)&w16v, g_w16v); cudaGetSymbolAddress((void**)&w16m, g_w16m);
    cudaGetSymbolAddress((void**)&w16a, g_w16a); cudaGetSymbolAddress((void**)&w16b, g_w16b);

    cudaFuncSetAttribute(attn_mma, cudaFuncAttributeMaxDynamicSharedMemorySize, SMEM_ATT);
    cudaFuncSetAttribute(gemm_qkv, cudaFuncAttributeMaxDynamicSharedMemorySize, SMEM_MMA);
    cudaFuncSetAttribute(gemm_f16<3,0>, cudaFuncAttributeMaxDynamicSharedMemorySize, SMEM_MMA);
    cudaFuncSetAttribute(gemm_f16<2,1>, cudaFuncAttributeMaxDynamicSharedMemorySize, SMEM_MMA);
    cudaFuncSetAttribute(gemm_f16<1,0>, cudaFuncAttributeMaxDynamicSharedMemorySize, SMEM_MMA);

    // fp32 -> fp16 converts: h (separate) + all six weights (one launch)
    {
        int n4 = MTOK * EE / 4;
        cvt16_kernel<<<(n4 + 255) / 256, 256>>>(h, h16, n4);
        int wtot = 4 * WSEG + 2 * WSEGB;
        cvtw_kernel<<<wtot / 256, 256>>>(wq, wk, wv, wmh, w1, w2,
                                         w16q, w16k, w16v, w16m, w16a, w16b);
    }

    dim3 blk(512);
    dim3 gQKV(EE / TN, MTOK / TM, 3);   // (4, 64, 3)
    dim3 gE(EE / TN, MTOK / TM);        // (4, 64)
    dim3 gHid(HIDD / TN, MTOK / TM);    // (16, 64)

    // QKV merged -> fp16
    gemm_qkv<<<gQKV, blk, SMEM_MMA>>>(h16, w16q, w16k, w16v,
                                      q16, k16, v16, MTOK, EE, EE);

    // attention -> o (fp16)
    attn_mma<<<dim3(HH, SS / 128, BB), dim3(256), SMEM_ATT>>>(mask, q16, k16, v16, o16);

    // mh + residual -> h2 (fp32)
    gemm_f16<3,0><<<gE, blk, SMEM_MMA>>>(o16, w16m, nullptr, h,
                                         h2, nullptr, MTOK, EE, EE);

    // attn_norm -> a fp32 + fp16
    ln_kernel<<<MTOK, 256>>>(h2, nullptr, nullptr, g1, be1, a, a16, 0);

    // FFN1 (+bias+GELU) -> hid fp16
    gemm_f16<2,1><<<gHid, blk, SMEM_MMA>>>(a16, w16a, b1, nullptr,
                                           nullptr, hid16, MTOK, HIDD, EE);
    // FFN2 (+bias) -> f fp32
    gemm_f16<1,0><<<gE, blk, SMEM_MMA>>>(hid16, w16b, b2, nullptr,
                                         f, nullptr, MTOK, EE, HIDD);

    // gated residual + ffn_norm -> out
    ln_kernel<<<MTOK, 256>>>(a, f, mask, g2, be2, out, nullptr, 1);
}